// round 11
// baseline (speedup 1.0000x reference)
#include <cuda_runtime.h>
#include <math.h>

#define NPTS   8192
#define NB     4
#define NPOINT 409
#define NQ     (NB*NPOINT)   // 1636
#define UNIBLK ((NQ + 7)/8)  // 205
#define FPS_CL 4             // FPS cluster size (CTAs per batch)
#define FPS_BLKS (NB*FPS_CL) // 16

// ---------------- device scratch (no allocations allowed) ----------------
__device__ double g_rep_sum;
__device__ double g_uni_sum[5];
__device__ float  g_newxyz[NQ*3];
__device__ unsigned int g_done;

// Exact (non-FMA-contracted) squared distance, matching XLA's sub->mul->add.
__device__ __forceinline__ float sqdist3(float ax,float ay,float az,
                                         float bx,float by,float bz){
    float dx=__fsub_rn(ax,bx), dy=__fsub_rn(ay,by), dz=__fsub_rn(az,bz);
    return __fadd_rn(__fadd_rn(__fmul_rn(dx,dx),__fmul_rn(dy,dy)),__fmul_rn(dz,dz));
}

// ---- cluster helpers ----
__device__ __forceinline__ unsigned int s2u(const void* p){
    unsigned int a;
    asm("{ .reg .u64 t; cvta.to.shared.u64 t, %1; cvt.u32.u64 %0, t; }" : "=r"(a) : "l"(p));
    return a;
}
__device__ __forceinline__ unsigned int ctarank(){
    unsigned int r; asm("mov.u32 %0, %%cluster_ctarank;" : "=r"(r)); return r;
}
// plain DSMEM store of one u64 into CTA `rank`'s smem (tag embedded in word; no fence)
__device__ __forceinline__ void slot_store(unsigned int slot_addr, unsigned long long v,
                                           unsigned int rank){
    unsigned int rs;
    asm volatile("mapa.shared::cluster.u32 %0, %1, %2;" : "=r"(rs) : "r"(slot_addr), "r"(rank));
    asm volatile("st.shared::cluster.u64 [%0], %1;" :: "r"(rs), "l"(v) : "memory");
}
__device__ __forceinline__ unsigned long long ld_slot_vol(unsigned int addr){
    unsigned long long v;
    asm volatile("ld.volatile.shared.u64 %0, [%1];" : "=l"(v) : "r"(addr));
    return v;
}
__device__ __forceinline__ void cluster_sync_all(){
    asm volatile("barrier.cluster.arrive.aligned;" ::: "memory");
    asm volatile("barrier.cluster.wait.aligned;"   ::: "memory");
}
__device__ __forceinline__ unsigned long long u64max(unsigned long long a, unsigned long long b){
    return (a>b)? a : b;
}

__global__ void init_kernel(){
    if (threadIdx.x==0){ g_rep_sum=0.0; g_done=0u; }
    if (threadIdx.x<5)  g_uni_sum[threadIdx.x]=0.0;
}

// =====================================================================
// Fused kernel (cluster dims 4): blocks 0..15 = FPS (4-CTA cluster per
// batch, fence-free tagged-word DSMEM argmax exchange).
// Blocks 16..143 = repulsion; hit body forced into a REAL branch (the
// dynamic while-loop insertion sort cannot be predicated) so the hot
// loop is just LDS.128 + exact sqdist + FSETP + rare @P BRA.
// =====================================================================
#define TILE 2048

__global__ __launch_bounds__(256,1) __cluster_dims__(FPS_CL,1,1)
void fps_rep_kernel(const float* __restrict__ pcd){
    __shared__ float4 s_tile[TILE];                          // repulsion role
    __shared__ __align__(8) unsigned long long s_slot[2][FPS_CL]; // published CTA-bests (parity)
    __shared__ __align__(8) unsigned long long s_loc[8];     // local warp bests
    __shared__ float s_red[8];
    const int tid = threadIdx.x;

    if (blockIdx.x < FPS_BLKS){
        // ---------------- FPS role: 4 CTAs per batch, 8 pts/thread ----------------
        const unsigned int rank = ctarank();                 // 0..3
        const int b = blockIdx.x / FPS_CL;
        const float* __restrict__ P = pcd + b*NPTS*3;
        const int pbase = (int)rank * (NPTS/FPS_CL);         // 2048-point chunk
        const int lane = tid & 31;
        const unsigned int slot0 = s2u(&s_slot[0][0]);

        float x[8], y[8], z[8], dmin[8];
        #pragma unroll
        for (int k=0;k<8;k++){
            const int j = pbase + tid + k*256;
            x[k]=P[3*j]; y[k]=P[3*j+1]; z[k]=P[3*j+2];
            dmin[k]=1e10f;
        }
        if (tid < 2*FPS_CL)                                  // invalid tag 511 (> max t=408)
            s_slot[tid>>2][tid&3] = 0x1FFull;
        __syncthreads();
        cluster_sync_all();                                  // inits visible before any publish

        float px=P[0], py=P[1], pz=P[2];
        for (int t=0;t<NPOINT;t++){
            if (rank==0 && tid==0){
                const int qi = b*NPOINT + t;
                g_newxyz[3*qi]=px; g_newxyz[3*qi+1]=py; g_newxyz[3*qi+2]=pz;
            }
            float bv=-1.f; int bj=0;
            #pragma unroll
            for (int k=0;k<8;k++){
                const float d  = sqdist3(x[k],y[k],z[k],px,py,pz);
                const float nd = fminf(dmin[k], d);
                dmin[k] = nd;
                if (nd > bv){ bv=nd; bj=pbase+tid+k*256; }   // strict > keeps lowest j in-thread
            }
            // warp argmax via redux (dmin>=0 so uint order == float order)
            const unsigned vb = __float_as_uint(bv);
            const unsigned mx = __reduce_max_sync(0xffffffffu, vb);
            const unsigned cand = (vb==mx)? (unsigned)bj : 0xffffffffu;
            const unsigned mnj = __reduce_min_sync(0xffffffffu, cand);
            const unsigned tag = (unsigned)t & 511u;
            if (lane==0)
                s_loc[tid>>5] = (((unsigned long long)mx)<<32)
                              | (((unsigned long long)(NPTS-1-(int)mnj))<<9)
                              | (unsigned long long)tag;
            __syncthreads();
            const int par = t & 1;
            if (tid==0){
                unsigned long long m = s_loc[0];
                #pragma unroll
                for (int k=1;k<8;k++) m = u64max(m, s_loc[k]);
                const unsigned int my = slot0 + (unsigned)((par*FPS_CL + (int)rank)*8);
                #pragma unroll
                for (unsigned int r=0;r<FPS_CL;r++) slot_store(my, m, r);  // one word per CTA
            }
            // consumers: poll local slots until all 4 carry this iteration's tag
            const unsigned int pb2 = slot0 + (unsigned)(par*FPS_CL*8);
            unsigned long long v0,v1,v2,v3;
            do {
                v0=ld_slot_vol(pb2); v1=ld_slot_vol(pb2+8);
                v2=ld_slot_vol(pb2+16); v3=ld_slot_vol(pb2+24);
            } while ((((unsigned)v0 ^ tag) & 511u) | (((unsigned)v1 ^ tag) & 511u) |
                     (((unsigned)v2 ^ tag) & 511u) | (((unsigned)v3 ^ tag) & 511u));
            const unsigned long long m0 = u64max(u64max(v0,v1), u64max(v2,v3));
            const int j = (NPTS-1) - (int)((m0>>9) & 0x1FFFull);
            px=P[3*j]; py=P[3*j+1]; pz=P[3*j+2];   // uniform-address broadcast load
        }
        cluster_sync_all();                        // no early exit with stores in flight
    } else {
        // ---------------- repulsion role (branch-forced hit body) ----------------
        const int rb = blockIdx.x - FPS_BLKS;  // 0..127, 32 blocks per batch
        const int b  = rb >> 5;
        const int i  = ((rb & 31) << 8) + tid; // point index 0..8191
        const float* __restrict__ P = pcd + b*NPTS*3;
        const float qx=P[3*i], qy=P[3*i+1], qz=P[3*i+2];
        const float R2 = (float)(0.07*0.07);
        float best[6];                         // [0..4] five smallest, [5] scratch
        #pragma unroll
        for (int k=0;k<5;k++) best[k]=3.4e38f;
        float h0 = 0.f; int cnt = 0;

        for (int base=0; base<NPTS; base+=TILE){
            for (int j=tid; j<TILE; j+=256){
                const int g = base + j;
                s_tile[j] = make_float4(P[3*g],P[3*g+1],P[3*g+2],0.f);
            }
            __syncthreads();
            #pragma unroll 4
            for (int j=0;j<TILE;j++){
                const float4 tp = s_tile[j];
                const float dd = sqdist3(qx,qy,qz,tp.x,tp.y,tp.z);
                if (dd<=R2){                       // rare (~1% taken per warp-point)
                    // dynamic while-loop => ptxas must emit a real branch, keeping
                    // the hot loop free of the predicated-off insertion ladder
                    if (cnt<20){
                        if (cnt==0) h0 = dd;
                        cnt++;
                        if (dd < best[4]){
                            best[4]=dd;
                            int k=3;
                            while (k>=0 && best[k+1]<best[k]){
                                float tm=best[k]; best[k]=best[k+1]; best[k+1]=tm; k--;
                            }
                        }
                    }
                }
            }
            __syncthreads();
        }
        // ballquery pads missing slots with the first hit
        for (int t=cnt; t<20; t++){
            if (!(h0 < best[4])) break;
            best[4]=h0;
            int k=3;
            while (k>=0 && best[k+1]<best[k]){
                float tm=best[k]; best[k]=best[k+1]; best[k+1]=tm; k--;
            }
        }
        const float H2 = (float)(0.03*0.03);
        float s = 0.f;
        #pragma unroll
        for (int k=1;k<5;k++){                   // drop smallest (self), keep next 4
            const float d5 = fmaxf(best[k], 0.f);
            const float ds = sqrtf(d5);
            const float w  = expf((-d5)/H2);
            s = __fadd_rn(s, __fsub_rn(0.07f, __fmul_rn(ds,w)));
        }
        #pragma unroll
        for (int o=16;o;o>>=1) s += __shfl_down_sync(0xffffffffu, s, o);
        if ((tid&31)==0) s_red[tid>>5] = s;
        __syncthreads();
        if (tid==0){
            float tt=0.f;
            #pragma unroll
            for (int w=0;w<8;w++) tt += s_red[w];
            atomicAdd(&g_rep_sum, (double)tt);
        }
    }
}

// =====================================================================
// Fused uniform loss (one coalesced scan per query for all 5 radii) +
// in-kernel finalization by the last block.
// =====================================================================
#define UCAP 192          // master hit-list capacity (actual hits ~<=25)

__global__ __launch_bounds__(256) void uni_fused_kernel(const float* __restrict__ pcd,
                                                        float* __restrict__ out){
    __shared__ float4        s_pts[8][UCAP];     // {x,y,z,d^2}
    __shared__ unsigned char s_sel[8][136];
    __shared__ float         s_acc[5];
    const int tid = threadIdx.x, lane = tid & 31, w = tid >> 5;
    if (tid < 5) s_acc[tid] = 0.f;
    __syncthreads();

    const int qi = blockIdx.x * 8 + w;
    float wsum[5] = {0.f,0.f,0.f,0.f,0.f};

    const double pv[5]  = {0.004,0.008,0.01,0.012,0.016};
    const int    nss[5] = {32,65,81,98,131};
    float r2s[5], expf_[5], denf_[5];
    #pragma unroll
    for (int i=0;i<5;i++){
        double r = sqrt(pv[i]*1.0);
        r2s[i] = (float)(r*r);
        double disk = 3.14159265358979323846 * 1.0 * pv[i] / (double)nss[i];
        double el   = sqrt(2.0*disk/1.732);
        expf_[i] = (float)el;
        denf_[i] = (float)(el + 1e-8);
    }
    const float r2max = r2s[4];

    if (qi < NQ){
        const int b = qi / NPOINT;
        const float* __restrict__ P = pcd + b*NPTS*3;
        const float qx=g_newxyz[3*qi], qy=g_newxyz[3*qi+1], qz=g_newxyz[3*qi+2];

        // ---- phase 1: coalesced scan + warp-ballot compaction ----
        int cnt = 0;
        for (int base=0; base<NPTS; base+=32){
            const int j = base + lane;
            const float px=P[3*j], py=P[3*j+1], pz=P[3*j+2];
            const float dd = sqdist3(px,py,pz,qx,qy,qz);
            const bool hit = (dd <= r2max);
            const unsigned msk = __ballot_sync(0xffffffffu, hit);
            if (hit){
                const int pos = cnt + __popc(msk & ((1u<<lane)-1u));
                if (pos < UCAP) s_pts[w][pos] = make_float4(px,py,pz,dd);
            }
            cnt += __popc(msk);
        }
        if (cnt > UCAP) cnt = UCAP;
        __syncwarp();

        // ---- phase 2: per percentage ----
        #pragma unroll
        for (int i=0;i<5;i++){
            const int   ns  = nss[i];
            const float r2  = r2s[i];
            int K = 0;
            for (int base=0; base<cnt && K<ns; base+=32){
                const int m = base + lane;
                const bool sel = (m < cnt) && (s_pts[w][m].w <= r2);
                const unsigned msk = __ballot_sync(0xffffffffu, sel);
                if (sel){
                    const int pos = K + __popc(msk & ((1u<<lane)-1u));
                    if (pos < ns) s_sel[w][pos] = (unsigned char)m;
                }
                K += __popc(msk);
            }
            if (K > ns) K = ns;
            __syncwarp();

            const int Ppad = ns - K;
            float s = 0.f;
            const float4 p0 = s_pts[w][s_sel[w][0]];
            for (int r = lane; r < K; r += 32){
                const float4 a = s_pts[w][s_sel[w][r]];
                float m1 = 3.4e38f, m2 = 3.4e38f;
                for (int bb=0; bb<K; bb++){
                    const float4 pb = s_pts[w][s_sel[w][bb]];
                    const float dd = sqdist3(a.x,a.y,a.z,pb.x,pb.y,pb.z);
                    if (dd < m1){ m2 = m1; m1 = dd; }
                    else if (dd < m2){ m2 = dd; }
                }
                if (Ppad > 0){
                    const float dd = sqdist3(a.x,a.y,a.z,p0.x,p0.y,p0.z);
                    if (dd < m1){ m2 = m1; m1 = dd; } else if (dd < m2){ m2 = dd; }
                    if (Ppad > 1){
                        if (dd < m1){ m2 = m1; m1 = dd; } else if (dd < m2){ m2 = dd; }
                    }
                }
                const float rud = sqrtf(fabsf(__fadd_rn(m2, 1e-8f)));
                const float dv  = __fsub_rn(rud, expf_[i]);
                s = __fadd_rn(s, __fmul_rn(dv,dv)/denf_[i]);
            }
            if (lane == 0 && Ppad > 0){
                const float rud = sqrtf(fabsf(__fadd_rn(0.f, 1e-8f)));
                const float dv  = __fsub_rn(rud, expf_[i]);
                s = __fadd_rn(s, (float)Ppad * (__fmul_rn(dv,dv)/denf_[i]));
            }
            #pragma unroll
            for (int o=16;o;o>>=1) s += __shfl_down_sync(0xffffffffu, s, o);
            wsum[i] = s;
            __syncwarp();
        }
        if (lane == 0){
            #pragma unroll
            for (int i=0;i<5;i++) atomicAdd(&s_acc[i], wsum[i]);
        }
    }
    __syncthreads();
    if (tid < 5) atomicAdd(&g_uni_sum[tid], (double)s_acc[tid]);
    __syncthreads();

    // ---- finalization by the last block to finish ----
    if (tid == 0){
        __threadfence();
        const unsigned v = atomicAdd(&g_done, 1u);
        if (v == (unsigned)(UNIBLK - 1)){
            const double pvf[5]  = {0.004,0.008,0.01,0.012,0.016};
            const int    nssf[5] = {32,65,81,98,131};
            double u = 0.0;
            for (int i=0;i<5;i++){
                const double m = g_uni_sum[i] / ((double)NQ * (double)nssf[i]);
                const double wgt = (pvf[i]*100.0)*(pvf[i]*100.0);
                u += m*wgt;
            }
            u /= 5.0;
            out[0] = (float)u;
            out[1] = (float)(g_rep_sum / 131072.0);   // mean over B*N*4
        }
    }
}

extern "C" void kernel_launch(void* const* d_in, const int* in_sizes, int n_in,
                              void* d_out, int out_size){
    (void)in_sizes; (void)n_in; (void)out_size;
    const float* pcd = (const float*)d_in[0];
    float* out = (float*)d_out;

    init_kernel<<<1,32>>>();
    fps_rep_kernel<<<FPS_BLKS + NB*32, 256>>>(pcd);  // 16 FPS (4 clusters of 4) + 128 repulsion
    uni_fused_kernel<<<UNIBLK, 256>>>(pcd, out);     // 205 blocks; last one finalizes
}

// round 12
// speedup vs baseline: 1.5232x; 1.5232x over previous
#include <cuda_runtime.h>
#include <math.h>

#define NPTS   8192
#define NB     4
#define NPOINT 409
#define NQ     (NB*NPOINT)   // 1636
#define UNIBLK ((NQ + 7)/8)  // 205
#define FPS_CL 4             // FPS cluster size (CTAs per batch)
#define FPS_BLKS (NB*FPS_CL) // 16

// ---- spatial grid for repulsion ballquery (cell 2/28 = 0.0714 > r = 0.07) ----
#define GD   28
#define GC   (GD*GD*GD)      // 21952 cells per batch
#define CCAP 12              // capacity per cell (lambda=0.373 -> P(overflow) ~ 0)

// ---------------- device scratch (no allocations allowed) ----------------
__device__ double g_rep_sum;
__device__ double g_uni_sum[5];
__device__ float  g_newxyz[NQ*3];
__device__ unsigned int g_done;
__device__ int    g_ccnt[NB*GC];           // per-cell counts
__device__ float4 g_cpts[NB*GC*CCAP];      // per-cell points {x,y,z,idx}

// Exact (non-FMA-contracted) squared distance, matching XLA's sub->mul->add.
__device__ __forceinline__ float sqdist3(float ax,float ay,float az,
                                         float bx,float by,float bz){
    float dx=__fsub_rn(ax,bx), dy=__fsub_rn(ay,by), dz=__fsub_rn(az,bz);
    return __fadd_rn(__fadd_rn(__fmul_rn(dx,dx),__fmul_rn(dy,dy)),__fmul_rn(dz,dz));
}

__device__ __forceinline__ int cell_of(float v){
    int c = (int)((v + 1.0f) * 14.0f);     // 14 = GD/2 (exact in f32)
    if (c < 0) c = 0; if (c > GD-1) c = GD-1;
    return c;
}

// ---- cluster helpers ----
__device__ __forceinline__ unsigned int s2u(const void* p){
    unsigned int a;
    asm("{ .reg .u64 t; cvta.to.shared.u64 t, %1; cvt.u32.u64 %0, t; }" : "=r"(a) : "l"(p));
    return a;
}
__device__ __forceinline__ unsigned int ctarank(){
    unsigned int r; asm("mov.u32 %0, %%cluster_ctarank;" : "=r"(r)); return r;
}
__device__ __forceinline__ void slot_store(unsigned int slot_addr, unsigned long long v,
                                           unsigned int rank){
    unsigned int rs;
    asm volatile("mapa.shared::cluster.u32 %0, %1, %2;" : "=r"(rs) : "r"(slot_addr), "r"(rank));
    asm volatile("st.shared::cluster.u64 [%0], %1;" :: "r"(rs), "l"(v) : "memory");
}
__device__ __forceinline__ unsigned long long ld_slot_vol(unsigned int addr){
    unsigned long long v;
    asm volatile("ld.volatile.shared.u64 %0, [%1];" : "=l"(v) : "r"(addr));
    return v;
}
__device__ __forceinline__ void cluster_sync_all(){
    asm volatile("barrier.cluster.arrive.aligned;" ::: "memory");
    asm volatile("barrier.cluster.wait.aligned;"   ::: "memory");
}
__device__ __forceinline__ unsigned long long u64max(unsigned long long a, unsigned long long b){
    return (a>b)? a : b;
}

// init: scalars + zero the grid counts (87808 ints over 32768 threads)
__global__ void init_kernel(){
    const int gid = blockIdx.x*256 + threadIdx.x;
    if (gid==0){ g_rep_sum=0.0; g_done=0u; }
    if (gid<5)  g_uni_sum[gid]=0.0;
    for (int c = gid; c < NB*GC; c += 128*256) g_ccnt[c] = 0;
}

// grid build: one-pass atomic scatter (order-independent final results downstream)
__global__ __launch_bounds__(256) void grid_build_kernel(const float* __restrict__ pcd){
    const int gid = blockIdx.x*256 + threadIdx.x;   // 0..32767
    const int b = gid / NPTS, j = gid % NPTS;
    const float x = pcd[(size_t)b*NPTS*3 + 3*j];
    const float y = pcd[(size_t)b*NPTS*3 + 3*j + 1];
    const float z = pcd[(size_t)b*NPTS*3 + 3*j + 2];
    const int cell = b*GC + (cell_of(z)*GD + cell_of(y))*GD + cell_of(x);
    const int slot = atomicAdd(&g_ccnt[cell], 1);
    if (slot < CCAP) g_cpts[(size_t)cell*CCAP + slot] = make_float4(x,y,z,__int_as_float(j));
}

// =====================================================================
// Fused kernel (cluster dims 4): blocks 0..15 = FPS (4-CTA cluster per
// batch, fence-free tagged-word DSMEM argmax exchange — proven R10).
// Blocks 16..143 = repulsion via GRID ballquery (~10 candidates/pt).
// =====================================================================
__global__ __launch_bounds__(256,1) __cluster_dims__(FPS_CL,1,1)
void fps_rep_kernel(const float* __restrict__ pcd){
    __shared__ __align__(8) unsigned long long s_slot[2][FPS_CL]; // published CTA-bests (parity)
    __shared__ __align__(8) unsigned long long s_loc[8];          // local warp bests
    __shared__ float s_red[8];
    const int tid = threadIdx.x;

    if (blockIdx.x < FPS_BLKS){
        // ---------------- FPS role: 4 CTAs per batch, 8 pts/thread ----------------
        const unsigned int rank = ctarank();                 // 0..3
        const int b = blockIdx.x / FPS_CL;
        const float* __restrict__ P = pcd + b*NPTS*3;
        const int pbase = (int)rank * (NPTS/FPS_CL);         // 2048-point chunk
        const int lane = tid & 31;
        const unsigned int slot0 = s2u(&s_slot[0][0]);

        float x[8], y[8], z[8], dmin[8];
        #pragma unroll
        for (int k=0;k<8;k++){
            const int j = pbase + tid + k*256;
            x[k]=P[3*j]; y[k]=P[3*j+1]; z[k]=P[3*j+2];
            dmin[k]=1e10f;
        }
        if (tid < 2*FPS_CL)                                  // invalid tag 511 (> max t=408)
            s_slot[tid>>2][tid&3] = 0x1FFull;
        __syncthreads();
        cluster_sync_all();                                  // inits visible before any publish

        float px=P[0], py=P[1], pz=P[2];
        for (int t=0;t<NPOINT;t++){
            if (rank==0 && tid==0){
                const int qi = b*NPOINT + t;
                g_newxyz[3*qi]=px; g_newxyz[3*qi+1]=py; g_newxyz[3*qi+2]=pz;
            }
            float bv=-1.f; int bj=0;
            #pragma unroll
            for (int k=0;k<8;k++){
                const float d  = sqdist3(x[k],y[k],z[k],px,py,pz);
                const float nd = fminf(dmin[k], d);
                dmin[k] = nd;
                if (nd > bv){ bv=nd; bj=pbase+tid+k*256; }   // strict > keeps lowest j in-thread
            }
            // warp argmax via redux (dmin>=0 so uint order == float order)
            const unsigned vb = __float_as_uint(bv);
            const unsigned mx = __reduce_max_sync(0xffffffffu, vb);
            const unsigned cand = (vb==mx)? (unsigned)bj : 0xffffffffu;
            const unsigned mnj = __reduce_min_sync(0xffffffffu, cand);
            const unsigned tag = (unsigned)t & 511u;
            if (lane==0)
                s_loc[tid>>5] = (((unsigned long long)mx)<<32)
                              | (((unsigned long long)(NPTS-1-(int)mnj))<<9)
                              | (unsigned long long)tag;
            __syncthreads();
            const int par = t & 1;
            if (tid==0){
                unsigned long long m = s_loc[0];
                #pragma unroll
                for (int k=1;k<8;k++) m = u64max(m, s_loc[k]);
                const unsigned int my = slot0 + (unsigned)((par*FPS_CL + (int)rank)*8);
                #pragma unroll
                for (unsigned int r=0;r<FPS_CL;r++) slot_store(my, m, r);  // one word per CTA
            }
            // consumers: poll local slots until all 4 carry this iteration's tag
            const unsigned int pb2 = slot0 + (unsigned)(par*FPS_CL*8);
            unsigned long long v0,v1,v2,v3;
            do {
                v0=ld_slot_vol(pb2); v1=ld_slot_vol(pb2+8);
                v2=ld_slot_vol(pb2+16); v3=ld_slot_vol(pb2+24);
            } while ((((unsigned)v0 ^ tag) & 511u) | (((unsigned)v1 ^ tag) & 511u) |
                     (((unsigned)v2 ^ tag) & 511u) | (((unsigned)v3 ^ tag) & 511u));
            const unsigned long long m0 = u64max(u64max(v0,v1), u64max(v2,v3));
            const int j = (NPTS-1) - (int)((m0>>9) & 0x1FFFull);
            px=P[3*j]; py=P[3*j+1]; pz=P[3*j+2];   // uniform-address broadcast load
        }
        cluster_sync_all();                        // no early exit with stores in flight
    } else {
        // ---------------- repulsion role: grid ballquery ----------------
        const int rb = blockIdx.x - FPS_BLKS;  // 0..127, 32 blocks per batch
        const int b  = rb >> 5;
        const int i  = ((rb & 31) << 8) + tid; // point index 0..8191
        const float* __restrict__ P = pcd + b*NPTS*3;
        const float qx=P[3*i], qy=P[3*i+1], qz=P[3*i+2];
        const float R2 = (float)(0.07*0.07);

        // first-20-hits-by-ascending-index list (exact ballquery semantics,
        // independent of nondeterministic grid fill order)
        int   idxl[20];
        float dl[20];
        int K = 0;
        const int cx = cell_of(qx), cy = cell_of(qy), cz = cell_of(qz);
        for (int dz=-1; dz<=1; dz++){
            const int zz = cz+dz; if (zz<0 || zz>=GD) continue;
            for (int dy=-1; dy<=1; dy++){
                const int yy = cy+dy; if (yy<0 || yy>=GD) continue;
                for (int dx=-1; dx<=1; dx++){
                    const int xx = cx+dx; if (xx<0 || xx>=GD) continue;
                    const int cell = b*GC + (zz*GD + yy)*GD + xx;
                    int n = g_ccnt[cell]; if (n > CCAP) n = CCAP;
                    const float4* __restrict__ cp = &g_cpts[(size_t)cell*CCAP];
                    for (int e=0;e<n;e++){
                        const float4 tp = cp[e];
                        const float dd = sqdist3(qx,qy,qz,tp.x,tp.y,tp.z);
                        if (dd <= R2){
                            const int jj = __float_as_int(tp.w);
                            if (K < 20){
                                int p = K-1;
                                while (p>=0 && idxl[p]>jj){ idxl[p+1]=idxl[p]; dl[p+1]=dl[p]; p--; }
                                idxl[p+1]=jj; dl[p+1]=dd; K++;
                            } else if (jj < idxl[19]){
                                int p = 18;
                                while (p>=0 && idxl[p]>jj){ idxl[p+1]=idxl[p]; dl[p+1]=dl[p]; p--; }
                                idxl[p+1]=jj; dl[p+1]=dd;
                            }
                        }
                    }
                }
            }
        }
        // 5 smallest of the (index-ordered) first-20 hits, then first-hit padding
        float best[5] = {3.4e38f,3.4e38f,3.4e38f,3.4e38f,3.4e38f};
        float h0 = (K>0)? dl[0] : 0.f;
        for (int k=0;k<K;k++){
            const float dd = dl[k];
            if (dd < best[4]){
                best[4]=dd;
                #pragma unroll
                for (int q=3;q>=0;q--){
                    if (best[q+1]<best[q]){ float tm=best[q]; best[q]=best[q+1]; best[q+1]=tm; }
                }
            }
        }
        for (int t=K; t<20; t++){
            if (!(h0 < best[4])) break;
            best[4]=h0;
            #pragma unroll
            for (int q=3;q>=0;q--){
                if (best[q+1]<best[q]){ float tm=best[q]; best[q]=best[q+1]; best[q+1]=tm; }
            }
        }
        const float H2 = (float)(0.03*0.03);
        float s = 0.f;
        #pragma unroll
        for (int k=1;k<5;k++){                   // drop smallest (self), keep next 4
            const float d5 = fmaxf(best[k], 0.f);
            const float ds = sqrtf(d5);
            const float w  = expf((-d5)/H2);
            s = __fadd_rn(s, __fsub_rn(0.07f, __fmul_rn(ds,w)));
        }
        #pragma unroll
        for (int o=16;o;o>>=1) s += __shfl_down_sync(0xffffffffu, s, o);
        if ((tid&31)==0) s_red[tid>>5] = s;
        __syncthreads();
        if (tid==0){
            float tt=0.f;
            #pragma unroll
            for (int w=0;w<8;w++) tt += s_red[w];
            atomicAdd(&g_rep_sum, (double)tt);
        }
    }
}

// =====================================================================
// Fused uniform loss (one coalesced scan per query for all 5 radii) +
// in-kernel finalization by the last block.
// =====================================================================
#define UCAP 192          // master hit-list capacity (actual hits ~<=25)

__global__ __launch_bounds__(256) void uni_fused_kernel(const float* __restrict__ pcd,
                                                        float* __restrict__ out){
    __shared__ float4        s_pts[8][UCAP];     // {x,y,z,d^2}
    __shared__ unsigned char s_sel[8][136];
    __shared__ float         s_acc[5];
    const int tid = threadIdx.x, lane = tid & 31, w = tid >> 5;
    if (tid < 5) s_acc[tid] = 0.f;
    __syncthreads();

    const int qi = blockIdx.x * 8 + w;
    float wsum[5] = {0.f,0.f,0.f,0.f,0.f};

    const double pv[5]  = {0.004,0.008,0.01,0.012,0.016};
    const int    nss[5] = {32,65,81,98,131};
    float r2s[5], expf_[5], denf_[5];
    #pragma unroll
    for (int i=0;i<5;i++){
        double r = sqrt(pv[i]*1.0);
        r2s[i] = (float)(r*r);
        double disk = 3.14159265358979323846 * 1.0 * pv[i] / (double)nss[i];
        double el   = sqrt(2.0*disk/1.732);
        expf_[i] = (float)el;
        denf_[i] = (float)(el + 1e-8);
    }
    const float r2max = r2s[4];

    if (qi < NQ){
        const int b = qi / NPOINT;
        const float* __restrict__ P = pcd + b*NPTS*3;
        const float qx=g_newxyz[3*qi], qy=g_newxyz[3*qi+1], qz=g_newxyz[3*qi+2];

        // ---- phase 1: coalesced scan + warp-ballot compaction ----
        int cnt = 0;
        for (int base=0; base<NPTS; base+=32){
            const int j = base + lane;
            const float px=P[3*j], py=P[3*j+1], pz=P[3*j+2];
            const float dd = sqdist3(px,py,pz,qx,qy,qz);
            const bool hit = (dd <= r2max);
            const unsigned msk = __ballot_sync(0xffffffffu, hit);
            if (hit){
                const int pos = cnt + __popc(msk & ((1u<<lane)-1u));
                if (pos < UCAP) s_pts[w][pos] = make_float4(px,py,pz,dd);
            }
            cnt += __popc(msk);
        }
        if (cnt > UCAP) cnt = UCAP;
        __syncwarp();

        // ---- phase 2: per percentage ----
        #pragma unroll
        for (int i=0;i<5;i++){
            const int   ns  = nss[i];
            const float r2  = r2s[i];
            int K = 0;
            for (int base=0; base<cnt && K<ns; base+=32){
                const int m = base + lane;
                const bool sel = (m < cnt) && (s_pts[w][m].w <= r2);
                const unsigned msk = __ballot_sync(0xffffffffu, sel);
                if (sel){
                    const int pos = K + __popc(msk & ((1u<<lane)-1u));
                    if (pos < ns) s_sel[w][pos] = (unsigned char)m;
                }
                K += __popc(msk);
            }
            if (K > ns) K = ns;
            __syncwarp();

            const int Ppad = ns - K;
            float s = 0.f;
            const float4 p0 = s_pts[w][s_sel[w][0]];
            for (int r = lane; r < K; r += 32){
                const float4 a = s_pts[w][s_sel[w][r]];
                float m1 = 3.4e38f, m2 = 3.4e38f;
                for (int bb=0; bb<K; bb++){
                    const float4 pb = s_pts[w][s_sel[w][bb]];
                    const float dd = sqdist3(a.x,a.y,a.z,pb.x,pb.y,pb.z);
                    if (dd < m1){ m2 = m1; m1 = dd; }
                    else if (dd < m2){ m2 = dd; }
                }
                if (Ppad > 0){
                    const float dd = sqdist3(a.x,a.y,a.z,p0.x,p0.y,p0.z);
                    if (dd < m1){ m2 = m1; m1 = dd; } else if (dd < m2){ m2 = dd; }
                    if (Ppad > 1){
                        if (dd < m1){ m2 = m1; m1 = dd; } else if (dd < m2){ m2 = dd; }
                    }
                }
                const float rud = sqrtf(fabsf(__fadd_rn(m2, 1e-8f)));
                const float dv  = __fsub_rn(rud, expf_[i]);
                s = __fadd_rn(s, __fmul_rn(dv,dv)/denf_[i]);
            }
            if (lane == 0 && Ppad > 0){
                const float rud = sqrtf(fabsf(__fadd_rn(0.f, 1e-8f)));
                const float dv  = __fsub_rn(rud, expf_[i]);
                s = __fadd_rn(s, (float)Ppad * (__fmul_rn(dv,dv)/denf_[i]));
            }
            #pragma unroll
            for (int o=16;o;o>>=1) s += __shfl_down_sync(0xffffffffu, s, o);
            wsum[i] = s;
            __syncwarp();
        }
        if (lane == 0){
            #pragma unroll
            for (int i=0;i<5;i++) atomicAdd(&s_acc[i], wsum[i]);
        }
    }
    __syncthreads();
    if (tid < 5) atomicAdd(&g_uni_sum[tid], (double)s_acc[tid]);
    __syncthreads();

    // ---- finalization by the last block to finish ----
    if (tid == 0){
        __threadfence();
        const unsigned v = atomicAdd(&g_done, 1u);
        if (v == (unsigned)(UNIBLK - 1)){
            const double pvf[5]  = {0.004,0.008,0.01,0.012,0.016};
            const int    nssf[5] = {32,65,81,98,131};
            double u = 0.0;
            for (int i=0;i<5;i++){
                const double m = g_uni_sum[i] / ((double)NQ * (double)nssf[i]);
                const double wgt = (pvf[i]*100.0)*(pvf[i]*100.0);
                u += m*wgt;
            }
            u /= 5.0;
            out[0] = (float)u;
            out[1] = (float)(g_rep_sum / 131072.0);   // mean over B*N*4
        }
    }
}

extern "C" void kernel_launch(void* const* d_in, const int* in_sizes, int n_in,
                              void* d_out, int out_size){
    (void)in_sizes; (void)n_in; (void)out_size;
    const float* pcd = (const float*)d_in[0];
    float* out = (float*)d_out;

    init_kernel<<<128,256>>>();                      // scalars + zero grid counts
    grid_build_kernel<<<NB*NPTS/256, 256>>>(pcd);    // atomic scatter into cells
    fps_rep_kernel<<<FPS_BLKS + NB*32, 256>>>(pcd);  // 16 FPS (clusters of 4) + 128 grid-repulsion
    uni_fused_kernel<<<UNIBLK, 256>>>(pcd, out);     // 205 blocks; last one finalizes
}

// round 13
// speedup vs baseline: 1.7778x; 1.1672x over previous
#include <cuda_runtime.h>
#include <math.h>

#define NPTS   8192
#define NB     4
#define NPOINT 409
#define NQ     (NB*NPOINT)   // 1636
#define UNIBLK ((NQ + 7)/8)  // 205
#define FPS_CL 4             // FPS cluster size (CTAs per batch)
#define FPS_BLKS (NB*FPS_CL) // 16

// ---- spatial grid (cell 2/28 = 0.0714): serves repulsion (r=0.07, +-1 cell)
// ---- and uniform loss (r_max=0.1265, +-2 cells)
#define GD   28
#define GC   (GD*GD*GD)      // 21952 cells per batch
#define CCAP 12              // capacity per cell (lambda=0.373 -> P(overflow) ~ 0)

// ---------------- device scratch (no allocations allowed) ----------------
__device__ double g_rep_sum;
__device__ double g_uni_sum[5];
__device__ float  g_newxyz[NQ*3];
__device__ unsigned int g_done;
__device__ int    g_ccnt[NB*GC];           // per-cell counts
__device__ float4 g_cpts[NB*GC*CCAP];      // per-cell points {x,y,z,idx}

// Exact (non-FMA-contracted) squared distance, matching XLA's sub->mul->add.
__device__ __forceinline__ float sqdist3(float ax,float ay,float az,
                                         float bx,float by,float bz){
    float dx=__fsub_rn(ax,bx), dy=__fsub_rn(ay,by), dz=__fsub_rn(az,bz);
    return __fadd_rn(__fadd_rn(__fmul_rn(dx,dx),__fmul_rn(dy,dy)),__fmul_rn(dz,dz));
}

__device__ __forceinline__ int cell_of(float v){
    int c = (int)((v + 1.0f) * 14.0f);     // 14 = GD/2 (exact in f32)
    if (c < 0) c = 0; if (c > GD-1) c = GD-1;
    return c;
}

// ---- cluster helpers ----
__device__ __forceinline__ unsigned int s2u(const void* p){
    unsigned int a;
    asm("{ .reg .u64 t; cvta.to.shared.u64 t, %1; cvt.u32.u64 %0, t; }" : "=r"(a) : "l"(p));
    return a;
}
__device__ __forceinline__ unsigned int ctarank(){
    unsigned int r; asm("mov.u32 %0, %%cluster_ctarank;" : "=r"(r)); return r;
}
__device__ __forceinline__ void slot_store(unsigned int slot_addr, unsigned long long v,
                                           unsigned int rank){
    unsigned int rs;
    asm volatile("mapa.shared::cluster.u32 %0, %1, %2;" : "=r"(rs) : "r"(slot_addr), "r"(rank));
    asm volatile("st.shared::cluster.u64 [%0], %1;" :: "r"(rs), "l"(v) : "memory");
}
__device__ __forceinline__ unsigned long long ld_slot_vol(unsigned int addr){
    unsigned long long v;
    asm volatile("ld.volatile.shared.u64 %0, [%1];" : "=l"(v) : "r"(addr));
    return v;
}
__device__ __forceinline__ void cluster_sync_all(){
    asm volatile("barrier.cluster.arrive.aligned;" ::: "memory");
    asm volatile("barrier.cluster.wait.aligned;"   ::: "memory");
}
__device__ __forceinline__ unsigned long long u64max(unsigned long long a, unsigned long long b){
    return (a>b)? a : b;
}

// init: scalars + zero the grid counts
__global__ void init_kernel(){
    const int gid = blockIdx.x*256 + threadIdx.x;
    if (gid==0){ g_rep_sum=0.0; g_done=0u; }
    if (gid<5)  g_uni_sum[gid]=0.0;
    for (int c = gid; c < NB*GC; c += 128*256) g_ccnt[c] = 0;
}

// grid build: one-pass atomic scatter (order-independent final results downstream)
__global__ __launch_bounds__(256) void grid_build_kernel(const float* __restrict__ pcd){
    const int gid = blockIdx.x*256 + threadIdx.x;   // 0..32767
    const int b = gid / NPTS, j = gid % NPTS;
    const float x = pcd[(size_t)b*NPTS*3 + 3*j];
    const float y = pcd[(size_t)b*NPTS*3 + 3*j + 1];
    const float z = pcd[(size_t)b*NPTS*3 + 3*j + 2];
    const int cell = b*GC + (cell_of(z)*GD + cell_of(y))*GD + cell_of(x);
    const int slot = atomicAdd(&g_ccnt[cell], 1);
    if (slot < CCAP) g_cpts[(size_t)cell*CCAP + slot] = make_float4(x,y,z,__int_as_float(j));
}

// =====================================================================
// Fused kernel (cluster dims 4): blocks 0..15 = FPS (proven R10 path).
// Blocks 16..143 = repulsion via GRID ballquery (proven R12 path).
// =====================================================================
__global__ __launch_bounds__(256,1) __cluster_dims__(FPS_CL,1,1)
void fps_rep_kernel(const float* __restrict__ pcd){
    __shared__ __align__(8) unsigned long long s_slot[2][FPS_CL]; // published CTA-bests (parity)
    __shared__ __align__(8) unsigned long long s_loc[8];          // local warp bests
    __shared__ float s_red[8];
    const int tid = threadIdx.x;

    if (blockIdx.x < FPS_BLKS){
        // ---------------- FPS role: 4 CTAs per batch, 8 pts/thread ----------------
        const unsigned int rank = ctarank();                 // 0..3
        const int b = blockIdx.x / FPS_CL;
        const float* __restrict__ P = pcd + b*NPTS*3;
        const int pbase = (int)rank * (NPTS/FPS_CL);         // 2048-point chunk
        const int lane = tid & 31;
        const unsigned int slot0 = s2u(&s_slot[0][0]);

        float x[8], y[8], z[8], dmin[8];
        #pragma unroll
        for (int k=0;k<8;k++){
            const int j = pbase + tid + k*256;
            x[k]=P[3*j]; y[k]=P[3*j+1]; z[k]=P[3*j+2];
            dmin[k]=1e10f;
        }
        if (tid < 2*FPS_CL)                                  // invalid tag 511 (> max t=408)
            s_slot[tid>>2][tid&3] = 0x1FFull;
        __syncthreads();
        cluster_sync_all();                                  // inits visible before any publish

        float px=P[0], py=P[1], pz=P[2];
        for (int t=0;t<NPOINT;t++){
            if (rank==0 && tid==0){
                const int qi = b*NPOINT + t;
                g_newxyz[3*qi]=px; g_newxyz[3*qi+1]=py; g_newxyz[3*qi+2]=pz;
            }
            float bv=-1.f; int bj=0;
            #pragma unroll
            for (int k=0;k<8;k++){
                const float d  = sqdist3(x[k],y[k],z[k],px,py,pz);
                const float nd = fminf(dmin[k], d);
                dmin[k] = nd;
                if (nd > bv){ bv=nd; bj=pbase+tid+k*256; }   // strict > keeps lowest j in-thread
            }
            // warp argmax via redux (dmin>=0 so uint order == float order)
            const unsigned vb = __float_as_uint(bv);
            const unsigned mx = __reduce_max_sync(0xffffffffu, vb);
            const unsigned cand = (vb==mx)? (unsigned)bj : 0xffffffffu;
            const unsigned mnj = __reduce_min_sync(0xffffffffu, cand);
            const unsigned tag = (unsigned)t & 511u;
            if (lane==0)
                s_loc[tid>>5] = (((unsigned long long)mx)<<32)
                              | (((unsigned long long)(NPTS-1-(int)mnj))<<9)
                              | (unsigned long long)tag;
            __syncthreads();
            const int par = t & 1;
            if (tid==0){
                unsigned long long m = s_loc[0];
                #pragma unroll
                for (int k=1;k<8;k++) m = u64max(m, s_loc[k]);
                const unsigned int my = slot0 + (unsigned)((par*FPS_CL + (int)rank)*8);
                #pragma unroll
                for (unsigned int r=0;r<FPS_CL;r++) slot_store(my, m, r);  // one word per CTA
            }
            // consumers: poll local slots until all 4 carry this iteration's tag
            const unsigned int pb2 = slot0 + (unsigned)(par*FPS_CL*8);
            unsigned long long v0,v1,v2,v3;
            do {
                v0=ld_slot_vol(pb2); v1=ld_slot_vol(pb2+8);
                v2=ld_slot_vol(pb2+16); v3=ld_slot_vol(pb2+24);
            } while ((((unsigned)v0 ^ tag) & 511u) | (((unsigned)v1 ^ tag) & 511u) |
                     (((unsigned)v2 ^ tag) & 511u) | (((unsigned)v3 ^ tag) & 511u));
            const unsigned long long m0 = u64max(u64max(v0,v1), u64max(v2,v3));
            const int j = (NPTS-1) - (int)((m0>>9) & 0x1FFFull);
            px=P[3*j]; py=P[3*j+1]; pz=P[3*j+2];   // uniform-address broadcast load
        }
        cluster_sync_all();                        // no early exit with stores in flight
    } else {
        // ---------------- repulsion role: grid ballquery ----------------
        const int rb = blockIdx.x - FPS_BLKS;  // 0..127, 32 blocks per batch
        const int b  = rb >> 5;
        const int i  = ((rb & 31) << 8) + tid; // point index 0..8191
        const float* __restrict__ P = pcd + b*NPTS*3;
        const float qx=P[3*i], qy=P[3*i+1], qz=P[3*i+2];
        const float R2 = (float)(0.07*0.07);

        // first-20-hits-by-ascending-index list (exact ballquery semantics,
        // independent of nondeterministic grid fill order)
        int   idxl[20];
        float dl[20];
        int K = 0;
        const int cx = cell_of(qx), cy = cell_of(qy), cz = cell_of(qz);
        for (int dz=-1; dz<=1; dz++){
            const int zz = cz+dz; if (zz<0 || zz>=GD) continue;
            for (int dy=-1; dy<=1; dy++){
                const int yy = cy+dy; if (yy<0 || yy>=GD) continue;
                for (int dx=-1; dx<=1; dx++){
                    const int xx = cx+dx; if (xx<0 || xx>=GD) continue;
                    const int cell = b*GC + (zz*GD + yy)*GD + xx;
                    int n = g_ccnt[cell]; if (n > CCAP) n = CCAP;
                    const float4* __restrict__ cp = &g_cpts[(size_t)cell*CCAP];
                    for (int e=0;e<n;e++){
                        const float4 tp = cp[e];
                        const float dd = sqdist3(qx,qy,qz,tp.x,tp.y,tp.z);
                        if (dd <= R2){
                            const int jj = __float_as_int(tp.w);
                            if (K < 20){
                                int p = K-1;
                                while (p>=0 && idxl[p]>jj){ idxl[p+1]=idxl[p]; dl[p+1]=dl[p]; p--; }
                                idxl[p+1]=jj; dl[p+1]=dd; K++;
                            } else if (jj < idxl[19]){
                                int p = 18;
                                while (p>=0 && idxl[p]>jj){ idxl[p+1]=idxl[p]; dl[p+1]=dl[p]; p--; }
                                idxl[p+1]=jj; dl[p+1]=dd;
                            }
                        }
                    }
                }
            }
        }
        // 5 smallest of the (index-ordered) first-20 hits, then first-hit padding
        float best[5] = {3.4e38f,3.4e38f,3.4e38f,3.4e38f,3.4e38f};
        float h0 = (K>0)? dl[0] : 0.f;
        for (int k=0;k<K;k++){
            const float dd = dl[k];
            if (dd < best[4]){
                best[4]=dd;
                #pragma unroll
                for (int q=3;q>=0;q--){
                    if (best[q+1]<best[q]){ float tm=best[q]; best[q]=best[q+1]; best[q+1]=tm; }
                }
            }
        }
        for (int t=K; t<20; t++){
            if (!(h0 < best[4])) break;
            best[4]=h0;
            #pragma unroll
            for (int q=3;q>=0;q--){
                if (best[q+1]<best[q]){ float tm=best[q]; best[q]=best[q+1]; best[q+1]=tm; }
            }
        }
        const float H2 = (float)(0.03*0.03);
        float s = 0.f;
        #pragma unroll
        for (int k=1;k<5;k++){                   // drop smallest (self), keep next 4
            const float d5 = fmaxf(best[k], 0.f);
            const float ds = sqrtf(d5);
            const float w  = expf((-d5)/H2);
            s = __fadd_rn(s, __fsub_rn(0.07f, __fmul_rn(ds,w)));
        }
        #pragma unroll
        for (int o=16;o;o>>=1) s += __shfl_down_sync(0xffffffffu, s, o);
        if ((tid&31)==0) s_red[tid>>5] = s;
        __syncthreads();
        if (tid==0){
            float tt=0.f;
            #pragma unroll
            for (int w=0;w<8;w++) tt += s_red[w];
            atomicAdd(&g_rep_sum, (double)tt);
        }
    }
}

// =====================================================================
// Fused uniform loss — GRID-based ballquery (±2 cells, ~47 candidates
// instead of 8192). Hits are sorted by point index (lane 0) to restore
// exact ascending-index ballquery semantics regardless of grid fill
// order. Phase 2 (filter + K x K 2-NN + analytic pads) unchanged.
// =====================================================================
#define UCAP 64           // master hit-list capacity (expected ~9 hits in r_max ball)

__global__ __launch_bounds__(256) void uni_fused_kernel(const float* __restrict__ pcd,
                                                        float* __restrict__ out){
    __shared__ float4        s_pts[8][UCAP];     // {x,y,z,d^2} sorted by index
    __shared__ int           s_idx[8][UCAP];
    __shared__ int           s_cnt[8];
    __shared__ unsigned char s_sel[8][136];
    __shared__ float         s_acc[5];
    const int tid = threadIdx.x, lane = tid & 31, w = tid >> 5;
    if (tid < 5) s_acc[tid] = 0.f;
    if (lane == 0) s_cnt[w] = 0;
    __syncthreads();

    const int qi = blockIdx.x * 8 + w;
    float wsum[5] = {0.f,0.f,0.f,0.f,0.f};

    const double pv[5]  = {0.004,0.008,0.01,0.012,0.016};
    const int    nss[5] = {32,65,81,98,131};
    float r2s[5], expf_[5], denf_[5];
    #pragma unroll
    for (int i=0;i<5;i++){
        double r = sqrt(pv[i]*1.0);
        r2s[i] = (float)(r*r);
        double disk = 3.14159265358979323846 * 1.0 * pv[i] / (double)nss[i];
        double el   = sqrt(2.0*disk/1.732);
        expf_[i] = (float)el;
        denf_[i] = (float)(el + 1e-8);
    }
    const float r2max = r2s[4];

    if (qi < NQ){
        const int b = qi / NPOINT;
        const float qx=g_newxyz[3*qi], qy=g_newxyz[3*qi+1], qz=g_newxyz[3*qi+2];

        // ---- phase 1: grid gather over 5x5x5 cells, lanes cooperative ----
        const int cx = cell_of(qx), cy = cell_of(qy), cz = cell_of(qz);
        for (int cc = lane; cc < 125; cc += 32){
            const int dzc =  cc/25 - 2;
            const int dyc = (cc/5)%5 - 2;
            const int dxc =  cc%5 - 2;
            const int zz = cz+dzc, yy = cy+dyc, xx = cx+dxc;
            if (zz<0 || zz>=GD || yy<0 || yy>=GD || xx<0 || xx>=GD) continue;
            const int cell = b*GC + (zz*GD + yy)*GD + xx;
            int n = g_ccnt[cell]; if (n > CCAP) n = CCAP;
            const float4* __restrict__ cp = &g_cpts[(size_t)cell*CCAP];
            for (int e=0;e<n;e++){
                const float4 tp = cp[e];
                const float dd = sqdist3(tp.x,tp.y,tp.z,qx,qy,qz);
                if (dd <= r2max){
                    const int pos = atomicAdd(&s_cnt[w], 1);
                    if (pos < UCAP){
                        s_pts[w][pos] = make_float4(tp.x,tp.y,tp.z,dd);
                        s_idx[w][pos] = __float_as_int(tp.w);
                    }
                }
            }
        }
        __syncwarp();
        int cnt = s_cnt[w]; if (cnt > UCAP) cnt = UCAP;
        // lane 0: insertion sort by point index (restores ascending-index order)
        if (lane == 0){
            for (int a=1;a<cnt;a++){
                const float4 pv4 = s_pts[w][a];
                const int    pi  = s_idx[w][a];
                int p = a-1;
                while (p>=0 && s_idx[w][p] > pi){
                    s_pts[w][p+1] = s_pts[w][p];
                    s_idx[w][p+1] = s_idx[w][p];
                    p--;
                }
                s_pts[w][p+1] = pv4;
                s_idx[w][p+1] = pi;
            }
        }
        __syncwarp();

        // ---- phase 2: per percentage (unchanged proven path) ----
        #pragma unroll
        for (int i=0;i<5;i++){
            const int   ns  = nss[i];
            const float r2  = r2s[i];
            int K = 0;
            for (int base=0; base<cnt && K<ns; base+=32){
                const int m = base + lane;
                const bool sel = (m < cnt) && (s_pts[w][m].w <= r2);
                const unsigned msk = __ballot_sync(0xffffffffu, sel);
                if (sel){
                    const int pos = K + __popc(msk & ((1u<<lane)-1u));
                    if (pos < ns) s_sel[w][pos] = (unsigned char)m;
                }
                K += __popc(msk);
            }
            if (K > ns) K = ns;
            __syncwarp();

            const int Ppad = ns - K;
            float s = 0.f;
            const float4 p0 = s_pts[w][s_sel[w][0]];
            for (int r = lane; r < K; r += 32){
                const float4 a = s_pts[w][s_sel[w][r]];
                float m1 = 3.4e38f, m2 = 3.4e38f;
                for (int bb=0; bb<K; bb++){
                    const float4 pb = s_pts[w][s_sel[w][bb]];
                    const float dd = sqdist3(a.x,a.y,a.z,pb.x,pb.y,pb.z);
                    if (dd < m1){ m2 = m1; m1 = dd; }
                    else if (dd < m2){ m2 = dd; }
                }
                if (Ppad > 0){
                    const float dd = sqdist3(a.x,a.y,a.z,p0.x,p0.y,p0.z);
                    if (dd < m1){ m2 = m1; m1 = dd; } else if (dd < m2){ m2 = dd; }
                    if (Ppad > 1){
                        if (dd < m1){ m2 = m1; m1 = dd; } else if (dd < m2){ m2 = dd; }
                    }
                }
                const float rud = sqrtf(fabsf(__fadd_rn(m2, 1e-8f)));
                const float dv  = __fsub_rn(rud, expf_[i]);
                s = __fadd_rn(s, __fmul_rn(dv,dv)/denf_[i]);
            }
            if (lane == 0 && Ppad > 0){
                const float rud = sqrtf(fabsf(__fadd_rn(0.f, 1e-8f)));
                const float dv  = __fsub_rn(rud, expf_[i]);
                s = __fadd_rn(s, (float)Ppad * (__fmul_rn(dv,dv)/denf_[i]));
            }
            #pragma unroll
            for (int o=16;o;o>>=1) s += __shfl_down_sync(0xffffffffu, s, o);
            wsum[i] = s;
            __syncwarp();
        }
        if (lane == 0){
            #pragma unroll
            for (int i=0;i<5;i++) atomicAdd(&s_acc[i], wsum[i]);
        }
    }
    __syncthreads();
    if (tid < 5) atomicAdd(&g_uni_sum[tid], (double)s_acc[tid]);
    __syncthreads();

    // ---- finalization by the last block to finish ----
    if (tid == 0){
        __threadfence();
        const unsigned v = atomicAdd(&g_done, 1u);
        if (v == (unsigned)(UNIBLK - 1)){
            const double pvf[5]  = {0.004,0.008,0.01,0.012,0.016};
            const int    nssf[5] = {32,65,81,98,131};
            double u = 0.0;
            for (int i=0;i<5;i++){
                const double m = g_uni_sum[i] / ((double)NQ * (double)nssf[i]);
                const double wgt = (pvf[i]*100.0)*(pvf[i]*100.0);
                u += m*wgt;
            }
            u /= 5.0;
            out[0] = (float)u;
            out[1] = (float)(g_rep_sum / 131072.0);   // mean over B*N*4
        }
    }
}

extern "C" void kernel_launch(void* const* d_in, const int* in_sizes, int n_in,
                              void* d_out, int out_size){
    (void)in_sizes; (void)n_in; (void)out_size;
    const float* pcd = (const float*)d_in[0];
    float* out = (float*)d_out;

    init_kernel<<<128,256>>>();                      // scalars + zero grid counts
    grid_build_kernel<<<NB*NPTS/256, 256>>>(pcd);    // atomic scatter into cells
    fps_rep_kernel<<<FPS_BLKS + NB*32, 256>>>(pcd);  // 16 FPS (clusters of 4) + 128 grid-repulsion
    uni_fused_kernel<<<UNIBLK, 256>>>(pcd, out);     // 205 blocks; last one finalizes
}

// round 14
// speedup vs baseline: 1.9239x; 1.0821x over previous
#include <cuda_runtime.h>
#include <math.h>

#define NPTS   8192
#define NB     4
#define NPOINT 409
#define NQ     (NB*NPOINT)   // 1636
#define UNIBLK ((NQ + 7)/8)  // 205
#define FPS_CL 4             // FPS cluster size (CTAs per batch)
#define FPS_BLKS (NB*FPS_CL) // 16

// ---- spatial grid (cell 2/28 = 0.0714): serves repulsion (r=0.07, +-1 cell)
// ---- and uniform loss (r_max=0.1265, +-2 cells)
#define GD   28
#define GC   (GD*GD*GD)      // 21952 cells per batch
#define CCAP 12              // capacity per cell (lambda=0.373 -> P(overflow) ~ 0)

// ---------------- device scratch (no allocations allowed) ----------------
__device__ double g_rep_part[16];
__device__ double g_uni_part[5][8];
__device__ float  g_newxyz[NQ*3];
__device__ unsigned int g_done;
__device__ int    g_ccnt[NB*GC];           // per-cell counts
__device__ float4 g_cpts[NB*GC*CCAP];      // per-cell points {x,y,z,idx}

// Exact (non-FMA-contracted) squared distance, matching XLA's sub->mul->add.
__device__ __forceinline__ float sqdist3(float ax,float ay,float az,
                                         float bx,float by,float bz){
    float dx=__fsub_rn(ax,bx), dy=__fsub_rn(ay,by), dz=__fsub_rn(az,bz);
    return __fadd_rn(__fadd_rn(__fmul_rn(dx,dx),__fmul_rn(dy,dy)),__fmul_rn(dz,dz));
}

__device__ __forceinline__ int cell_of(float v){
    int c = (int)((v + 1.0f) * 14.0f);     // 14 = GD/2 (exact in f32)
    if (c < 0) c = 0; if (c > GD-1) c = GD-1;
    return c;
}

// ---- cluster helpers ----
__device__ __forceinline__ unsigned int s2u(const void* p){
    unsigned int a;
    asm("{ .reg .u64 t; cvta.to.shared.u64 t, %1; cvt.u32.u64 %0, t; }" : "=r"(a) : "l"(p));
    return a;
}
__device__ __forceinline__ unsigned int ctarank(){
    unsigned int r; asm("mov.u32 %0, %%cluster_ctarank;" : "=r"(r)); return r;
}
__device__ __forceinline__ void slot_store(unsigned int slot_addr, unsigned long long v,
                                           unsigned int rank){
    unsigned int rs;
    asm volatile("mapa.shared::cluster.u32 %0, %1, %2;" : "=r"(rs) : "r"(slot_addr), "r"(rank));
    asm volatile("st.shared::cluster.u64 [%0], %1;" :: "r"(rs), "l"(v) : "memory");
}
__device__ __forceinline__ unsigned long long ld_slot_vol(unsigned int addr){
    unsigned long long v;
    asm volatile("ld.volatile.shared.u64 %0, [%1];" : "=l"(v) : "r"(addr));
    return v;
}
__device__ __forceinline__ void cluster_sync_all(){
    asm volatile("barrier.cluster.arrive.aligned;" ::: "memory");
    asm volatile("barrier.cluster.wait.aligned;"   ::: "memory");
}

// init: scalars + partial-sum slots + zero the grid counts
__global__ void init_kernel(){
    const int gid = blockIdx.x*256 + threadIdx.x;
    if (gid==0) g_done=0u;
    if (gid<16) g_rep_part[gid]=0.0;
    if (gid<40) g_uni_part[gid/8][gid&7]=0.0;
    for (int c = gid; c < NB*GC; c += 128*256) g_ccnt[c] = 0;
}

// grid build: one-pass atomic scatter (order-independent final results downstream)
__global__ __launch_bounds__(256) void grid_build_kernel(const float* __restrict__ pcd){
    const int gid = blockIdx.x*256 + threadIdx.x;   // 0..32767
    const int b = gid / NPTS, j = gid % NPTS;
    const float x = pcd[(size_t)b*NPTS*3 + 3*j];
    const float y = pcd[(size_t)b*NPTS*3 + 3*j + 1];
    const float z = pcd[(size_t)b*NPTS*3 + 3*j + 2];
    const int cell = b*GC + (cell_of(z)*GD + cell_of(y))*GD + cell_of(x);
    const int slot = atomicAdd(&g_ccnt[cell], 1);
    if (slot < CCAP) g_cpts[(size_t)cell*CCAP + slot] = make_float4(x,y,z,__int_as_float(j));
}

// =====================================================================
// Fused kernel (cluster dims 4): blocks 0..15 = FPS. NEW exchange:
// each warp leader publishes its warp-best directly to all 4 CTAs
// (32 tagged slots); no __syncthreads / tid0 stage in the chain.
// Consumption: lane k polls slot k, __all_sync tag check, then
// 2-stage __reduce_max_sync == exact u64 (val, min-index) argmax.
// Blocks 16..143 = repulsion via GRID ballquery (proven R12/13 path).
// =====================================================================
__global__ __launch_bounds__(256,1) __cluster_dims__(FPS_CL,1,1)
void fps_rep_kernel(const float* __restrict__ pcd){
    __shared__ __align__(8) unsigned long long s_slot[2][32]; // parity x (rank*8+warp)
    __shared__ float s_red[8];
    const int tid = threadIdx.x;

    if (blockIdx.x < FPS_BLKS){
        // ---------------- FPS role: 4 CTAs per batch, 8 pts/thread ----------------
        const unsigned int rank = ctarank();                 // 0..3
        const int b = blockIdx.x / FPS_CL;
        const float* __restrict__ P = pcd + b*NPTS*3;
        const int pbase = (int)rank * (NPTS/FPS_CL);         // 2048-point chunk
        const int lane = tid & 31, wid = tid >> 5;
        const unsigned int slot0 = s2u(&s_slot[0][0]);

        float x[8], y[8], z[8], dmin[8];
        #pragma unroll
        for (int k=0;k<8;k++){
            const int j = pbase + tid + k*256;
            x[k]=P[3*j]; y[k]=P[3*j+1]; z[k]=P[3*j+2];
            dmin[k]=1e10f;
        }
        if (tid < 64)                                        // invalid tag 511 (> max t=408)
            s_slot[tid>>5][tid&31] = 0x1FFull;
        __syncthreads();
        cluster_sync_all();                                  // inits visible before any publish

        float px=P[0], py=P[1], pz=P[2];
        for (int t=0;t<NPOINT;t++){
            if (rank==0 && tid==0){
                const int qi = b*NPOINT + t;
                g_newxyz[3*qi]=px; g_newxyz[3*qi+1]=py; g_newxyz[3*qi+2]=pz;
            }
            float bv=-1.f; int bj=0;
            #pragma unroll
            for (int k=0;k<8;k++){
                const float d  = sqdist3(x[k],y[k],z[k],px,py,pz);
                const float nd = fminf(dmin[k], d);
                dmin[k] = nd;
                if (nd > bv){ bv=nd; bj=pbase+tid+k*256; }   // strict > keeps lowest j in-thread
            }
            // warp argmax via redux (dmin>=0 so uint order == float order)
            const unsigned vb = __float_as_uint(bv);
            const unsigned mx = __reduce_max_sync(0xffffffffu, vb);
            const unsigned cand = (vb==mx)? (unsigned)bj : 0xffffffffu;
            const unsigned mnj = __reduce_min_sync(0xffffffffu, cand);
            const unsigned tag = (unsigned)t & 511u;
            const int par = t & 1;
            if (lane==0){
                // pack: [val:32 | inv_idx:13 | tag:9]  (u64 order == (val, min idx))
                const unsigned long long pk =
                    (((unsigned long long)mx)<<32)
                  | (((unsigned long long)(NPTS-1-(int)mnj))<<9)
                  | (unsigned long long)tag;
                const unsigned int my = slot0 + (unsigned)((par*32 + (int)rank*8 + wid)*8);
                #pragma unroll
                for (unsigned int r=0;r<FPS_CL;r++) slot_store(my, pk, r);
            }
            // consume: lane k polls slot k until every slot carries this tag
            const unsigned int myaddr = slot0 + (unsigned)(par*256) + (unsigned)(lane*8);
            unsigned long long v;
            bool ok;
            do {
                v  = ld_slot_vol(myaddr);
                ok = ((((unsigned)v) ^ tag) & 511u) == 0u;
            } while (!__all_sync(0xffffffffu, ok));
            const unsigned hi = (unsigned)(v>>32), lo = (unsigned)v;
            const unsigned mxhi = __reduce_max_sync(0xffffffffu, hi);
            const unsigned cl   = (hi==mxhi)? lo : 0u;
            const unsigned mxlo = __reduce_max_sync(0xffffffffu, cl);
            const int j = (NPTS-1) - (int)(mxlo>>9);
            px=P[3*j]; py=P[3*j+1]; pz=P[3*j+2];   // uniform-address broadcast load
        }
        cluster_sync_all();                        // no early exit with stores in flight
    } else {
        // ---------------- repulsion role: grid ballquery ----------------
        const int rb = blockIdx.x - FPS_BLKS;  // 0..127, 32 blocks per batch
        const int b  = rb >> 5;
        const int i  = ((rb & 31) << 8) + tid; // point index 0..8191
        const float* __restrict__ P = pcd + b*NPTS*3;
        const float qx=P[3*i], qy=P[3*i+1], qz=P[3*i+2];
        const float R2 = (float)(0.07*0.07);

        // first-20-hits-by-ascending-index list (exact ballquery semantics,
        // independent of nondeterministic grid fill order)
        int   idxl[20];
        float dl[20];
        int K = 0;
        const int cx = cell_of(qx), cy = cell_of(qy), cz = cell_of(qz);
        for (int dz=-1; dz<=1; dz++){
            const int zz = cz+dz; if (zz<0 || zz>=GD) continue;
            for (int dy=-1; dy<=1; dy++){
                const int yy = cy+dy; if (yy<0 || yy>=GD) continue;
                for (int dx=-1; dx<=1; dx++){
                    const int xx = cx+dx; if (xx<0 || xx>=GD) continue;
                    const int cell = b*GC + (zz*GD + yy)*GD + xx;
                    int n = g_ccnt[cell]; if (n > CCAP) n = CCAP;
                    const float4* __restrict__ cp = &g_cpts[(size_t)cell*CCAP];
                    for (int e=0;e<n;e++){
                        const float4 tp = cp[e];
                        const float dd = sqdist3(qx,qy,qz,tp.x,tp.y,tp.z);
                        if (dd <= R2){
                            const int jj = __float_as_int(tp.w);
                            if (K < 20){
                                int p = K-1;
                                while (p>=0 && idxl[p]>jj){ idxl[p+1]=idxl[p]; dl[p+1]=dl[p]; p--; }
                                idxl[p+1]=jj; dl[p+1]=dd; K++;
                            } else if (jj < idxl[19]){
                                int p = 18;
                                while (p>=0 && idxl[p]>jj){ idxl[p+1]=idxl[p]; dl[p+1]=dl[p]; p--; }
                                idxl[p+1]=jj; dl[p+1]=dd;
                            }
                        }
                    }
                }
            }
        }
        // 5 smallest of the (index-ordered) first-20 hits, then first-hit padding
        float best[5] = {3.4e38f,3.4e38f,3.4e38f,3.4e38f,3.4e38f};
        float h0 = (K>0)? dl[0] : 0.f;
        for (int k=0;k<K;k++){
            const float dd = dl[k];
            if (dd < best[4]){
                best[4]=dd;
                #pragma unroll
                for (int q=3;q>=0;q--){
                    if (best[q+1]<best[q]){ float tm=best[q]; best[q]=best[q+1]; best[q+1]=tm; }
                }
            }
        }
        for (int t=K; t<20; t++){
            if (!(h0 < best[4])) break;
            best[4]=h0;
            #pragma unroll
            for (int q=3;q>=0;q--){
                if (best[q+1]<best[q]){ float tm=best[q]; best[q]=best[q+1]; best[q+1]=tm; }
            }
        }
        const float H2 = (float)(0.03*0.03);
        float s = 0.f;
        #pragma unroll
        for (int k=1;k<5;k++){                   // drop smallest (self), keep next 4
            const float d5 = fmaxf(best[k], 0.f);
            const float ds = sqrtf(d5);
            const float w  = expf((-d5)/H2);
            s = __fadd_rn(s, __fsub_rn(0.07f, __fmul_rn(ds,w)));
        }
        #pragma unroll
        for (int o=16;o;o>>=1) s += __shfl_down_sync(0xffffffffu, s, o);
        if ((tid&31)==0) s_red[tid>>5] = s;
        __syncthreads();
        if (tid==0){
            float tt=0.f;
            #pragma unroll
            for (int w=0;w<8;w++) tt += s_red[w];
            atomicAdd(&g_rep_part[rb & 15], (double)tt);   // 16-way spread
        }
    }
}

// =====================================================================
// Fused uniform loss — GRID-based ballquery (±2 cells). Partial sums
// spread over 5x8 slots; last block finalizes.
// =====================================================================
#define UCAP 64           // master hit-list capacity (expected ~9 hits in r_max ball)

__global__ __launch_bounds__(256) void uni_fused_kernel(const float* __restrict__ pcd,
                                                        float* __restrict__ out){
    __shared__ float4        s_pts[8][UCAP];     // {x,y,z,d^2} sorted by index
    __shared__ int           s_idx[8][UCAP];
    __shared__ int           s_cnt[8];
    __shared__ unsigned char s_sel[8][136];
    __shared__ float         s_acc[5];
    const int tid = threadIdx.x, lane = tid & 31, w = tid >> 5;
    if (tid < 5) s_acc[tid] = 0.f;
    if (lane == 0) s_cnt[w] = 0;
    __syncthreads();

    const int qi = blockIdx.x * 8 + w;
    float wsum[5] = {0.f,0.f,0.f,0.f,0.f};

    const double pv[5]  = {0.004,0.008,0.01,0.012,0.016};
    const int    nss[5] = {32,65,81,98,131};
    float r2s[5], expf_[5], denf_[5];
    #pragma unroll
    for (int i=0;i<5;i++){
        double r = sqrt(pv[i]*1.0);
        r2s[i] = (float)(r*r);
        double disk = 3.14159265358979323846 * 1.0 * pv[i] / (double)nss[i];
        double el   = sqrt(2.0*disk/1.732);
        expf_[i] = (float)el;
        denf_[i] = (float)(el + 1e-8);
    }
    const float r2max = r2s[4];

    if (qi < NQ){
        const int b = qi / NPOINT;
        const float qx=g_newxyz[3*qi], qy=g_newxyz[3*qi+1], qz=g_newxyz[3*qi+2];

        // ---- phase 1: grid gather over 5x5x5 cells, lanes cooperative ----
        const int cx = cell_of(qx), cy = cell_of(qy), cz = cell_of(qz);
        for (int cc = lane; cc < 125; cc += 32){
            const int dzc =  cc/25 - 2;
            const int dyc = (cc/5)%5 - 2;
            const int dxc =  cc%5 - 2;
            const int zz = cz+dzc, yy = cy+dyc, xx = cx+dxc;
            if (zz<0 || zz>=GD || yy<0 || yy>=GD || xx<0 || xx>=GD) continue;
            const int cell = b*GC + (zz*GD + yy)*GD + xx;
            int n = g_ccnt[cell]; if (n > CCAP) n = CCAP;
            const float4* __restrict__ cp = &g_cpts[(size_t)cell*CCAP];
            for (int e=0;e<n;e++){
                const float4 tp = cp[e];
                const float dd = sqdist3(tp.x,tp.y,tp.z,qx,qy,qz);
                if (dd <= r2max){
                    const int pos = atomicAdd(&s_cnt[w], 1);
                    if (pos < UCAP){
                        s_pts[w][pos] = make_float4(tp.x,tp.y,tp.z,dd);
                        s_idx[w][pos] = __float_as_int(tp.w);
                    }
                }
            }
        }
        __syncwarp();
        int cnt = s_cnt[w]; if (cnt > UCAP) cnt = UCAP;
        // lane 0: insertion sort by point index (restores ascending-index order)
        if (lane == 0){
            for (int a=1;a<cnt;a++){
                const float4 pv4 = s_pts[w][a];
                const int    pi  = s_idx[w][a];
                int p = a-1;
                while (p>=0 && s_idx[w][p] > pi){
                    s_pts[w][p+1] = s_pts[w][p];
                    s_idx[w][p+1] = s_idx[w][p];
                    p--;
                }
                s_pts[w][p+1] = pv4;
                s_idx[w][p+1] = pi;
            }
        }
        __syncwarp();

        // ---- phase 2: per percentage (unchanged proven path) ----
        #pragma unroll
        for (int i=0;i<5;i++){
            const int   ns  = nss[i];
            const float r2  = r2s[i];
            int K = 0;
            for (int base=0; base<cnt && K<ns; base+=32){
                const int m = base + lane;
                const bool sel = (m < cnt) && (s_pts[w][m].w <= r2);
                const unsigned msk = __ballot_sync(0xffffffffu, sel);
                if (sel){
                    const int pos = K + __popc(msk & ((1u<<lane)-1u));
                    if (pos < ns) s_sel[w][pos] = (unsigned char)m;
                }
                K += __popc(msk);
            }
            if (K > ns) K = ns;
            __syncwarp();

            const int Ppad = ns - K;
            float s = 0.f;
            const float4 p0 = s_pts[w][s_sel[w][0]];
            for (int r = lane; r < K; r += 32){
                const float4 a = s_pts[w][s_sel[w][r]];
                float m1 = 3.4e38f, m2 = 3.4e38f;
                for (int bb=0; bb<K; bb++){
                    const float4 pb = s_pts[w][s_sel[w][bb]];
                    const float dd = sqdist3(a.x,a.y,a.z,pb.x,pb.y,pb.z);
                    if (dd < m1){ m2 = m1; m1 = dd; }
                    else if (dd < m2){ m2 = dd; }
                }
                if (Ppad > 0){
                    const float dd = sqdist3(a.x,a.y,a.z,p0.x,p0.y,p0.z);
                    if (dd < m1){ m2 = m1; m1 = dd; } else if (dd < m2){ m2 = dd; }
                    if (Ppad > 1){
                        if (dd < m1){ m2 = m1; m1 = dd; } else if (dd < m2){ m2 = dd; }
                    }
                }
                const float rud = sqrtf(fabsf(__fadd_rn(m2, 1e-8f)));
                const float dv  = __fsub_rn(rud, expf_[i]);
                s = __fadd_rn(s, __fmul_rn(dv,dv)/denf_[i]);
            }
            if (lane == 0 && Ppad > 0){
                const float rud = sqrtf(fabsf(__fadd_rn(0.f, 1e-8f)));
                const float dv  = __fsub_rn(rud, expf_[i]);
                s = __fadd_rn(s, (float)Ppad * (__fmul_rn(dv,dv)/denf_[i]));
            }
            #pragma unroll
            for (int o=16;o;o>>=1) s += __shfl_down_sync(0xffffffffu, s, o);
            wsum[i] = s;
            __syncwarp();
        }
        if (lane == 0){
            #pragma unroll
            for (int i=0;i<5;i++) atomicAdd(&s_acc[i], wsum[i]);
        }
    }
    __syncthreads();
    if (tid < 5) atomicAdd(&g_uni_part[tid][blockIdx.x & 7], (double)s_acc[tid]); // 8-way spread
    __syncthreads();

    // ---- finalization by the last block to finish ----
    if (tid == 0){
        __threadfence();
        const unsigned v = atomicAdd(&g_done, 1u);
        if (v == (unsigned)(UNIBLK - 1)){
            const double pvf[5]  = {0.004,0.008,0.01,0.012,0.016};
            const int    nssf[5] = {32,65,81,98,131};
            double u = 0.0;
            for (int i=0;i<5;i++){
                double ssum = 0.0;
                #pragma unroll
                for (int k=0;k<8;k++) ssum += g_uni_part[i][k];
                const double m = ssum / ((double)NQ * (double)nssf[i]);
                const double wgt = (pvf[i]*100.0)*(pvf[i]*100.0);
                u += m*wgt;
            }
            u /= 5.0;
            double rsum = 0.0;
            #pragma unroll
            for (int k=0;k<16;k++) rsum += g_rep_part[k];
            out[0] = (float)u;
            out[1] = (float)(rsum / 131072.0);        // mean over B*N*4
        }
    }
}

extern "C" void kernel_launch(void* const* d_in, const int* in_sizes, int n_in,
                              void* d_out, int out_size){
    (void)in_sizes; (void)n_in; (void)out_size;
    const float* pcd = (const float*)d_in[0];
    float* out = (float*)d_out;

    init_kernel<<<128,256>>>();                      // scalars + zero grid counts
    grid_build_kernel<<<NB*NPTS/256, 256>>>(pcd);    // atomic scatter into cells
    fps_rep_kernel<<<FPS_BLKS + NB*32, 256>>>(pcd);  // 16 FPS (clusters of 4) + 128 grid-repulsion
    uni_fused_kernel<<<UNIBLK, 256>>>(pcd, out);     // 205 blocks; last one finalizes
}